// round 1
// baseline (speedup 1.0000x reference)
#include <cuda_runtime.h>
#include <math.h>

#define H 1024
#define F 128
#define F4 32            // F_DIM/4 (Wt hidden)
#define MAXS 8192
#define NPART 256

// Scratch (no allocations allowed) — fully rewritten every call => deterministic.
__device__ float g_partial[NPART * H];
__device__ float g_gw[H];
__device__ float g_mrow[MAXS];

// ---------------------------------------------------------------------------
// K1: partial column sums of query (S x H). Each block handles a row chunk;
// thread t owns float4 column group t (columns 4t..4t+3).
// ---------------------------------------------------------------------------
__global__ void k1_qsum(const float4* __restrict__ q4, int S) {
    int b = blockIdx.x;
    int t = threadIdx.x;
    int rows = (S + gridDim.x - 1) / gridDim.x;
    int r0 = b * rows;
    int r1 = min(S, r0 + rows);
    float4 acc = make_float4(0.f, 0.f, 0.f, 0.f);
    for (int r = r0; r < r1; ++r) {
        float4 v = q4[(size_t)r * (H / 4) + t];
        acc.x += v.x; acc.y += v.y; acc.z += v.z; acc.w += v.w;
    }
    ((float4*)g_partial)[b * (H / 4) + t] = acc;
}

// ---------------------------------------------------------------------------
// K2: single block, 256 threads. Finishes qmean, tiny MLPs, produces g_gw.
// Assumes K_ANCHORS == 2 (problem constant).
// ---------------------------------------------------------------------------
__global__ void k2_small(const float* __restrict__ ts,  const float* __restrict__ dg,
                         const float* __restrict__ Wt1, const float* __restrict__ bt1,
                         const float* __restrict__ Wt2, const float* __restrict__ bt2,
                         const float* __restrict__ Wa1, const float* __restrict__ ba1,
                         const float* __restrict__ Wa2, const float* __restrict__ ba2,
                         const float* __restrict__ Wg,  const float* __restrict__ bg,
                         int S) {
    __shared__ float qmean[H];
    __shared__ float mem[2 * F];
    __shared__ float red[256];
    __shared__ float qpart[F];
    __shared__ float wgt[2];
    __shared__ float cm[F];
    __shared__ float cw_s;

    int t = threadIdx.x;

    // A: finish qmean reduction over NPART partials (float4 lanes)
    {
        float4 s = make_float4(0.f, 0.f, 0.f, 0.f);
        const float4* p4 = (const float4*)g_partial;
        #pragma unroll 8
        for (int b = 0; b < NPART; ++b) {
            float4 v = p4[b * (H / 4) + t];
            s.x += v.x; s.y += v.y; s.z += v.z; s.w += v.w;
        }
        float inv = 1.0f / (float)S;
        ((float4*)qmean)[t] = make_float4(s.x * inv, s.y * inv, s.z * inv, s.w * inv);
    }
    __syncthreads();

    // B: mem[k][h] = dg[k][h] + temporal MLP  (thread -> (k,h))
    {
        int k = t >> 7, h = t & 127;
        float tk = ts[k];
        float acc = bt2[h];
        #pragma unroll
        for (int j = 0; j < F4; ++j) {
            float a = fmaxf(fmaf(tk, Wt1[j], bt1[j]), 0.f);
            acc = fmaf(a, Wt2[j * F + h], acc);
        }
        mem[t] = dg[k * F + h] + acc;
    }

    // C1: qpart[j] = sum_h qmean[h] * Wa1[128+h][j]  (shared across anchors)
    {
        int j = t & 127, half = t >> 7;
        float acc = 0.f;
        int h0 = half * (H / 2);
        for (int h = h0; h < h0 + H / 2; ++h)
            acc = fmaf(qmean[h], Wa1[(F + h) * F + j], acc);
        red[t] = acc;
    }
    __syncthreads();
    if (t < F) qpart[t] = red[t] + red[t + F];
    __syncthreads();

    // C2: score per (k,j) then reduce over j -> weight[k]
    {
        int k = t >> 7, j = t & 127;
        float acc = ba1[j] + qpart[j];
        #pragma unroll 8
        for (int f = 0; f < F; ++f)
            acc = fmaf(mem[k * F + f], Wa1[f * F + j], acc);
        red[t] = tanhf(acc) * Wa2[j];
    }
    __syncthreads();
    for (int off = 64; off; off >>= 1) {
        if ((t & 127) < off) red[t] += red[t + off];
        __syncthreads();
    }
    if ((t & 127) == 0)
        wgt[t >> 7] = 1.f / (1.f + expf(-(red[t] + ba2[0])));
    __syncthreads();

    // D: collapse anchors: cm[f] = (1/2) sum_k w_k * mem[k][f]; cw = (1/2) sum_k w_k
    if (t < F) cm[t] = 0.5f * (wgt[0] * mem[t] + wgt[1] * mem[F + t]);
    if (t == 0) cw_s = 0.5f * (wgt[0] + wgt[1]);
    __syncthreads();

    // gw[h] = cw*bg[h] + sum_f cm[f] * Wg[f][h]   (thread t owns float4 group t)
    {
        float4 acc = make_float4(0.f, 0.f, 0.f, 0.f);
        const float4* Wg4 = (const float4*)Wg;
        #pragma unroll 4
        for (int f = 0; f < F; ++f) {
            float c = cm[f];
            float4 w = Wg4[f * (H / 4) + t];
            acc.x = fmaf(c, w.x, acc.x);
            acc.y = fmaf(c, w.y, acc.y);
            acc.z = fmaf(c, w.z, acc.z);
            acc.w = fmaf(c, w.w, acc.w);
        }
        float4 b = ((const float4*)bg)[t];
        float cw = cw_s;
        ((float4*)g_gw)[t] = make_float4(acc.x + cw * b.x, acc.y + cw * b.y,
                                         acc.z + cw * b.z, acc.w + cw * b.w);
    }
}

// ---------------------------------------------------------------------------
// K3: mean_row[s] = dot(gw, key[s])  — one warp per row, float4 loads.
// ---------------------------------------------------------------------------
__global__ void k3_matvec(const float4* __restrict__ key4, int S) {
    int warp = (blockIdx.x * blockDim.x + threadIdx.x) >> 5;
    int lane = threadIdx.x & 31;
    if (warp >= S) return;
    const float4* k4 = key4 + (size_t)warp * (H / 4);
    const float4* g4 = (const float4*)g_gw;
    float acc = 0.f;
    #pragma unroll
    for (int i = 0; i < (H / 4) / 32; ++i) {
        int idx = i * 32 + lane;
        float4 a = k4[idx];
        float4 b = g4[idx];
        acc = fmaf(a.x, b.x, acc);
        acc = fmaf(a.y, b.y, acc);
        acc = fmaf(a.z, b.z, acc);
        acc = fmaf(a.w, b.w, acc);
    }
    #pragma unroll
    for (int off = 16; off; off >>= 1) acc += __shfl_xor_sync(0xFFFFFFFFu, acc, off);
    if (lane == 0) g_mrow[warp] = acc;
}

// ---------------------------------------------------------------------------
// K4: broadcast mean_row into every output row (256 MB of float4 stores).
// One block per output row; mean_row stays L1-resident.
// ---------------------------------------------------------------------------
__global__ void k4_bcast(float* __restrict__ out, int S) {
    int row = blockIdx.x;
    const float4* m4 = (const float4*)g_mrow;
    float4* o4 = (float4*)(out + (size_t)row * S);
    int n4 = S >> 2;
    for (int c = threadIdx.x; c < n4; c += blockDim.x)
        o4[c] = m4[c];
}

// ---------------------------------------------------------------------------
extern "C" void kernel_launch(void* const* d_in, const int* in_sizes, int n_in,
                              void* d_out, int out_size) {
    const float* query = (const float*)d_in[0];
    const float* key   = (const float*)d_in[1];
    const float* dg    = (const float*)d_in[2];
    const float* ts    = (const float*)d_in[3];
    const float* Wt1   = (const float*)d_in[4];
    const float* bt1   = (const float*)d_in[5];
    const float* Wt2   = (const float*)d_in[6];
    const float* bt2   = (const float*)d_in[7];
    const float* Wa1   = (const float*)d_in[8];
    const float* ba1   = (const float*)d_in[9];
    const float* Wa2   = (const float*)d_in[10];
    const float* ba2   = (const float*)d_in[11];
    const float* Wg    = (const float*)d_in[12];
    const float* bg    = (const float*)d_in[13];

    int S = in_sizes[1] / H;   // key element count / H_DIM

    k1_qsum<<<NPART, 256>>>((const float4*)query, S);
    k2_small<<<1, 256>>>(ts, dg, Wt1, bt1, Wt2, bt2, Wa1, ba1, Wa2, ba2, Wg, bg, S);
    k3_matvec<<<(S + 7) / 8, 256>>>((const float4*)key, S);
    k4_bcast<<<S, 256>>>((float*)d_out, S);
}

// round 2
// speedup vs baseline: 1.7589x; 1.7589x over previous
#include <cuda_runtime.h>
#include <math.h>

#define H 1024
#define F 128
#define F4 32
#define MAXS 8192
#define NPART 256

// Scratch (fully rewritten every call => deterministic).
__device__ float g_partial[NPART * H];
__device__ float g_qp[32 * F];     // per-block qpart partials
__device__ float g_cm[F];
__device__ float g_cw;
__device__ float g_gw[H];
__device__ float g_mrow[MAXS];

// ---------------------------------------------------------------------------
// K1: partial column sums of query (S x H). 256 blocks x 256 threads.
// ---------------------------------------------------------------------------
__global__ void k1_qsum(const float4* __restrict__ q4, int S) {
    int b = blockIdx.x;
    int t = threadIdx.x;
    int rows = (S + gridDim.x - 1) / gridDim.x;
    int r0 = b * rows;
    int r1 = min(S, r0 + rows);
    float4 acc = make_float4(0.f, 0.f, 0.f, 0.f);
    for (int r = r0; r < r1; ++r) {
        float4 v = q4[(size_t)r * (H / 4) + t];
        acc.x += v.x; acc.y += v.y; acc.z += v.z; acc.w += v.w;
    }
    ((float4*)g_partial)[b * (H / 4) + t] = acc;
}

// ---------------------------------------------------------------------------
// K2a: 32 blocks x 256 threads. Block b owns h-slice [32b, 32b+32):
//   1) reduce qmean for those 32 h over the 256 partials
//   2) partial qpart[j] += qmean[h] * Wa1[(128+h)*128 + j]
// ---------------------------------------------------------------------------
__global__ void k2a_qpart(const float* __restrict__ Wa1, int S) {
    __shared__ float qm[32];
    __shared__ float red[256];
    int b = blockIdx.x, t = threadIdx.x;
    int h0 = b * 32;

    // qmean reduce: thread t = (p_lane<<5)|hl ; p_lane strides 8 over 256 partials
    {
        int hl = t & 31;
        float s = 0.f;
        for (int p = (t >> 5); p < NPART; p += 8)
            s += g_partial[p * H + h0 + hl];
        red[t] = s;
        __syncthreads();
        if (t < 128) red[t] += red[t + 128];
        __syncthreads();
        if (t < 64) red[t] += red[t + 64];
        __syncthreads();
        if (t < 32) qm[t] = (red[t] + red[t + 32]) / (float)S;
        __syncthreads();
    }

    // partial qpart: j = t&127, half handles 16 h each
    {
        int j = t & 127, half = t >> 7;
        float acc = 0.f;
        int hs = half * 16;
        #pragma unroll
        for (int hl = hs; hl < hs + 16; ++hl)
            acc = fmaf(qm[hl], Wa1[(size_t)(F + h0 + hl) * F + j], acc);
        red[t] = acc;
        __syncthreads();
        if (t < 128) g_qp[b * F + t] = red[t] + red[t + 128];
    }
}

// ---------------------------------------------------------------------------
// K2b: single block, 256 threads. Tiny scalar work -> cm, cw.
// ---------------------------------------------------------------------------
__global__ void k2b_small(const float* __restrict__ ts,  const float* __restrict__ dg,
                          const float* __restrict__ Wt1, const float* __restrict__ bt1,
                          const float* __restrict__ Wt2, const float* __restrict__ bt2,
                          const float* __restrict__ Wa1, const float* __restrict__ ba1,
                          const float* __restrict__ Wa2, const float* __restrict__ ba2) {
    __shared__ float qpart[F];
    __shared__ float mem[2 * F];
    __shared__ float red[256];
    __shared__ float wgt[2];

    int t = threadIdx.x;

    // finish qpart reduction over 32 block-partials
    if (t < F) {
        float s = 0.f;
        #pragma unroll
        for (int b = 0; b < 32; ++b) s += g_qp[b * F + t];
        qpart[t] = s;
    }

    // mem[k][h] = dg + temporal MLP  (t -> (k = t>>7, h = t&127))
    {
        int k = t >> 7, h = t & 127;
        float tk = ts[k];
        float acc = bt2[h];
        #pragma unroll
        for (int j = 0; j < F4; ++j) {
            float a = fmaxf(fmaf(tk, Wt1[j], bt1[j]), 0.f);
            acc = fmaf(a, Wt2[j * F + h], acc);
        }
        mem[t] = dg[k * F + h] + acc;
    }
    __syncthreads();

    // score per (k,j), reduce over j -> weight[k]
    {
        int k = t >> 7, j = t & 127;
        float acc = ba1[j] + qpart[j];
        #pragma unroll 8
        for (int f = 0; f < F; ++f)
            acc = fmaf(mem[k * F + f], Wa1[(size_t)f * F + j], acc);
        red[t] = tanhf(acc) * Wa2[j];
    }
    __syncthreads();
    for (int off = 64; off; off >>= 1) {
        if ((t & 127) < off) red[t] += red[t + off];
        __syncthreads();
    }
    if ((t & 127) == 0)
        wgt[t >> 7] = 1.f / (1.f + expf(-(red[t] + ba2[0])));
    __syncthreads();

    if (t < F) g_cm[t] = 0.5f * (wgt[0] * mem[t] + wgt[1] * mem[F + t]);
    if (t == 0) g_cw = 0.5f * (wgt[0] + wgt[1]);
}

// ---------------------------------------------------------------------------
// K2c: 32 blocks x 128 threads. Block b owns h-slice [32b, 32b+32);
// thread (fq = t>>5) handles 32 f values, shared-reduce 4 groups.
// ---------------------------------------------------------------------------
__global__ void k2c_gw(const float* __restrict__ Wg, const float* __restrict__ bg) {
    __shared__ float red[128];
    int b = blockIdx.x, t = threadIdx.x;
    int h = b * 32 + (t & 31);
    int f0 = (t >> 5) * 32;
    float acc = 0.f;
    #pragma unroll
    for (int f = f0; f < f0 + 32; ++f)
        acc = fmaf(g_cm[f], Wg[(size_t)f * H + h], acc);
    red[t] = acc;
    __syncthreads();
    if (t < 32)
        g_gw[h] = red[t] + red[t + 32] + red[t + 64] + red[t + 96]
                + g_cw * bg[h];
}

// ---------------------------------------------------------------------------
// K3: mean_row[s] = dot(gw, key[s])  — one warp per row, float4 loads.
// ---------------------------------------------------------------------------
__global__ void k3_matvec(const float4* __restrict__ key4, int S) {
    int warp = (blockIdx.x * blockDim.x + threadIdx.x) >> 5;
    int lane = threadIdx.x & 31;
    if (warp >= S) return;
    const float4* k4 = key4 + (size_t)warp * (H / 4);
    const float4* g4 = (const float4*)g_gw;
    float acc = 0.f;
    #pragma unroll
    for (int i = 0; i < (H / 4) / 32; ++i) {
        int idx = i * 32 + lane;
        float4 a = k4[idx];
        float4 b = g4[idx];
        acc = fmaf(a.x, b.x, acc);
        acc = fmaf(a.y, b.y, acc);
        acc = fmaf(a.z, b.z, acc);
        acc = fmaf(a.w, b.w, acc);
    }
    #pragma unroll
    for (int off = 16; off; off >>= 1) acc += __shfl_xor_sync(0xFFFFFFFFu, acc, off);
    if (lane == 0) g_mrow[warp] = acc;
}

// ---------------------------------------------------------------------------
// K4: broadcast mean_row into every output row. Streaming float4 stores.
// ---------------------------------------------------------------------------
__global__ void k4_bcast(float* __restrict__ out, int S) {
    int row = blockIdx.x;
    const float4* m4 = (const float4*)g_mrow;
    float4* o4 = (float4*)(out + (size_t)row * S);
    int n4 = S >> 2;
    for (int c = threadIdx.x; c < n4; c += blockDim.x) {
        float4 v = __ldg(m4 + c);
        __stcs(o4 + c, v);
    }
}

// ---------------------------------------------------------------------------
extern "C" void kernel_launch(void* const* d_in, const int* in_sizes, int n_in,
                              void* d_out, int out_size) {
    const float* query = (const float*)d_in[0];
    const float* key   = (const float*)d_in[1];
    const float* dg    = (const float*)d_in[2];
    const float* ts    = (const float*)d_in[3];
    const float* Wt1   = (const float*)d_in[4];
    const float* bt1   = (const float*)d_in[5];
    const float* Wt2   = (const float*)d_in[6];
    const float* bt2   = (const float*)d_in[7];
    const float* Wa1   = (const float*)d_in[8];
    const float* ba1   = (const float*)d_in[9];
    const float* Wa2   = (const float*)d_in[10];
    const float* ba2   = (const float*)d_in[11];
    const float* Wg    = (const float*)d_in[12];
    const float* bg    = (const float*)d_in[13];

    int S = in_sizes[1] / H;

    k1_qsum<<<NPART, 256>>>((const float4*)query, S);
    k2a_qpart<<<32, 256>>>(Wa1, S);
    k2b_small<<<1, 256>>>(ts, dg, Wt1, bt1, Wt2, bt2, Wa1, ba1, Wa2, ba2);
    k2c_gw<<<32, 128>>>(Wg, bg);
    k3_matvec<<<(S + 7) / 8, 256>>>((const float4*)key, S);
    k4_bcast<<<S, 256>>>((float*)d_out, S);
}

// round 3
// speedup vs baseline: 1.8304x; 1.0407x over previous
#include <cuda_runtime.h>
#include <math.h>

#define H 1024
#define F 128
#define F4 32
#define MAXS 8192
#define NPART 256

// Scratch (fully rewritten every call => deterministic).
__device__ float g_partial[NPART * H];
__device__ float g_qp[32 * F];
__device__ float g_w[2];          // 0.5 * sigmoid(score_k)
__device__ float g_v0[H];         // Wg^T mem_0 + bg
__device__ float g_v1[H];         // Wg^T mem_1 + bg
__device__ float g_r0[MAXS];      // v0 . key[s]
__device__ float g_r1[MAXS];      // v1 . key[s]

// ---------------------------------------------------------------------------
// Shared helper: temporal MLP -> mem[2*F] in shared (256 threads).
// ---------------------------------------------------------------------------
__device__ __forceinline__ void compute_mem(float* mem,
                                            const float* ts, const float* dg,
                                            const float* Wt1, const float* bt1,
                                            const float* Wt2, const float* bt2,
                                            int t) {
    int k = t >> 7, h = t & 127;
    float tk = ts[k];
    float acc = bt2[h];
    #pragma unroll
    for (int j = 0; j < F4; ++j) {
        float a = fmaxf(fmaf(tk, Wt1[j], bt1[j]), 0.f);
        acc = fmaf(a, Wt2[j * F + h], acc);
    }
    mem[t] = dg[k * F + h] + acc;
}

// ---------------------------------------------------------------------------
// K0 (branch A): v_k[h] = sum_f mem_k[f]*Wg[f][h] + bg[h].
// 32 blocks x 256 threads; block owns 32 h-cols; Wg read ONCE for both anchors.
// ---------------------------------------------------------------------------
__global__ void k0_vk(const float* __restrict__ ts,  const float* __restrict__ dg,
                      const float* __restrict__ Wt1, const float* __restrict__ bt1,
                      const float* __restrict__ Wt2, const float* __restrict__ bt2,
                      const float* __restrict__ Wg,  const float* __restrict__ bg) {
    __shared__ float mem[2 * F];
    __shared__ float red0[256];
    __shared__ float red1[256];
    int t = threadIdx.x;
    compute_mem(mem, ts, dg, Wt1, bt1, Wt2, bt2, t);
    __syncthreads();

    int hcol = blockIdx.x * 32 + (t & 31);
    int fg = t >> 5;                 // 8 groups of 16 f
    float a0 = 0.f, a1 = 0.f;
    #pragma unroll
    for (int f = fg * 16; f < fg * 16 + 16; ++f) {
        float w = Wg[(size_t)f * H + hcol];
        a0 = fmaf(mem[f], w, a0);
        a1 = fmaf(mem[F + f], w, a1);
    }
    red0[t] = a0; red1[t] = a1;
    __syncthreads();
    if (t < 128) { red0[t] += red0[t + 128]; red1[t] += red1[t + 128]; }
    __syncthreads();
    if (t < 64)  { red0[t] += red0[t + 64];  red1[t] += red1[t + 64]; }
    __syncthreads();
    if (t < 32) {
        float b = bg[hcol];
        g_v0[hcol] = red0[t] + red0[t + 32] + b;
        g_v1[hcol] = red1[t] + red1[t + 32] + b;
    }
}

// ---------------------------------------------------------------------------
// KB (branch A): dual matvec r0[s]=v0.key[s], r1[s]=v1.key[s]. Warp per row.
// ---------------------------------------------------------------------------
__global__ void kB_dualmv(const float4* __restrict__ key4, int S) {
    int warp = (blockIdx.x * blockDim.x + threadIdx.x) >> 5;
    int lane = threadIdx.x & 31;
    if (warp >= S) return;
    const float4* k4 = key4 + (size_t)warp * (H / 4);
    const float4* v04 = (const float4*)g_v0;
    const float4* v14 = (const float4*)g_v1;
    float a0 = 0.f, a1 = 0.f;
    #pragma unroll
    for (int i = 0; i < (H / 4) / 32; ++i) {
        int idx = i * 32 + lane;
        float4 kv = k4[idx];
        float4 x = __ldg(v04 + idx);
        float4 y = __ldg(v14 + idx);
        a0 = fmaf(kv.x, x.x, a0); a0 = fmaf(kv.y, x.y, a0);
        a0 = fmaf(kv.z, x.z, a0); a0 = fmaf(kv.w, x.w, a0);
        a1 = fmaf(kv.x, y.x, a1); a1 = fmaf(kv.y, y.y, a1);
        a1 = fmaf(kv.z, y.z, a1); a1 = fmaf(kv.w, y.w, a1);
    }
    #pragma unroll
    for (int off = 16; off; off >>= 1) {
        a0 += __shfl_xor_sync(0xFFFFFFFFu, a0, off);
        a1 += __shfl_xor_sync(0xFFFFFFFFu, a1, off);
    }
    if (lane == 0) { g_r0[warp] = a0; g_r1[warp] = a1; }
}

// ---------------------------------------------------------------------------
// K1 (branch B): partial column sums of query.
// ---------------------------------------------------------------------------
__global__ void k1_qsum(const float4* __restrict__ q4, int S) {
    int b = blockIdx.x;
    int t = threadIdx.x;
    int rows = (S + gridDim.x - 1) / gridDim.x;
    int r0 = b * rows;
    int r1 = min(S, r0 + rows);
    float4 acc = make_float4(0.f, 0.f, 0.f, 0.f);
    for (int r = r0; r < r1; ++r) {
        float4 v = q4[(size_t)r * (H / 4) + t];
        acc.x += v.x; acc.y += v.y; acc.z += v.z; acc.w += v.w;
    }
    ((float4*)g_partial)[b * (H / 4) + t] = acc;
}

// ---------------------------------------------------------------------------
// K2a (branch B): per-block qpart partials over Wa1 query half.
// ---------------------------------------------------------------------------
__global__ void k2a_qpart(const float* __restrict__ Wa1, int S) {
    __shared__ float qm[32];
    __shared__ float red[256];
    int b = blockIdx.x, t = threadIdx.x;
    int h0 = b * 32;
    {
        int hl = t & 31;
        float s = 0.f;
        for (int p = (t >> 5); p < NPART; p += 8)
            s += g_partial[p * H + h0 + hl];
        red[t] = s;
        __syncthreads();
        if (t < 128) red[t] += red[t + 128];
        __syncthreads();
        if (t < 64) red[t] += red[t + 64];
        __syncthreads();
        if (t < 32) qm[t] = (red[t] + red[t + 32]) / (float)S;
        __syncthreads();
    }
    {
        int j = t & 127, half = t >> 7;
        float acc = 0.f;
        int hs = half * 16;
        #pragma unroll
        for (int hl = hs; hl < hs + 16; ++hl)
            acc = fmaf(qm[hl], Wa1[(size_t)(F + h0 + hl) * F + j], acc);
        red[t] = acc;
        __syncthreads();
        if (t < 128) g_qp[b * F + t] = red[t] + red[t + 128];
    }
}

// ---------------------------------------------------------------------------
// K2b (branch B): single block -> scores -> g_w[k] = 0.5*sigmoid(score_k).
// ---------------------------------------------------------------------------
__global__ void k2b_small(const float* __restrict__ ts,  const float* __restrict__ dg,
                          const float* __restrict__ Wt1, const float* __restrict__ bt1,
                          const float* __restrict__ Wt2, const float* __restrict__ bt2,
                          const float* __restrict__ Wa1, const float* __restrict__ ba1,
                          const float* __restrict__ Wa2, const float* __restrict__ ba2) {
    __shared__ float qpart[F];
    __shared__ float mem[2 * F];
    __shared__ float red[256];
    int t = threadIdx.x;

    if (t < F) {
        float s = 0.f;
        #pragma unroll
        for (int b = 0; b < 32; ++b) s += g_qp[b * F + t];
        qpart[t] = s;
    }
    compute_mem(mem, ts, dg, Wt1, bt1, Wt2, bt2, t);
    __syncthreads();

    {
        int k = t >> 7, j = t & 127;
        float acc = ba1[j] + qpart[j];
        #pragma unroll 8
        for (int f = 0; f < F; ++f)
            acc = fmaf(mem[k * F + f], Wa1[(size_t)f * F + j], acc);
        red[t] = tanhf(acc) * Wa2[j];
    }
    __syncthreads();
    for (int off = 64; off; off >>= 1) {
        if ((t & 127) < off) red[t] += red[t + off];
        __syncthreads();
    }
    if ((t & 127) == 0)
        g_w[t >> 7] = 0.5f / (1.f + expf(-(red[t] + ba2[0])));
}

// ---------------------------------------------------------------------------
// K4 (join): out[row][s] = w0*r0[s] + w1*r1[s], streaming float4 stores.
// ---------------------------------------------------------------------------
__global__ void k4_bcast(float* __restrict__ out, int S) {
    __shared__ float wsh[2];
    if (threadIdx.x < 2) wsh[threadIdx.x] = g_w[threadIdx.x];
    __syncthreads();
    float w0 = wsh[0], w1 = wsh[1];
    int row = blockIdx.x;
    const float4* r04 = (const float4*)g_r0;
    const float4* r14 = (const float4*)g_r1;
    float4* o4 = (float4*)(out + (size_t)row * S);
    int n4 = S >> 2;
    for (int c = threadIdx.x; c < n4; c += blockDim.x) {
        float4 a = __ldg(r04 + c);
        float4 b = __ldg(r14 + c);
        float4 v;
        v.x = fmaf(w0, a.x, w1 * b.x);
        v.y = fmaf(w0, a.y, w1 * b.y);
        v.z = fmaf(w0, a.z, w1 * b.z);
        v.w = fmaf(w0, a.w, w1 * b.w);
        __stcs(o4 + c, v);
    }
}

// ---------------------------------------------------------------------------
extern "C" void kernel_launch(void* const* d_in, const int* in_sizes, int n_in,
                              void* d_out, int out_size) {
    const float* query = (const float*)d_in[0];
    const float* key   = (const float*)d_in[1];
    const float* dg    = (const float*)d_in[2];
    const float* ts    = (const float*)d_in[3];
    const float* Wt1   = (const float*)d_in[4];
    const float* bt1   = (const float*)d_in[5];
    const float* Wt2   = (const float*)d_in[6];
    const float* bt2   = (const float*)d_in[7];
    const float* Wa1   = (const float*)d_in[8];
    const float* ba1   = (const float*)d_in[9];
    const float* Wa2   = (const float*)d_in[10];
    const float* ba2   = (const float*)d_in[11];
    const float* Wg    = (const float*)d_in[12];
    const float* bg    = (const float*)d_in[13];

    int S = in_sizes[1] / H;

    // Host-side stream/event infrastructure, created once on the first
    // (uncaptured correctness) call; no device memory involved.
    static cudaStream_t s2 = nullptr;
    static cudaEvent_t evFork = nullptr, evJoin = nullptr;
    if (!s2) {
        cudaStreamCreateWithFlags(&s2, cudaStreamNonBlocking);
        cudaEventCreateWithFlags(&evFork, cudaEventDisableTiming);
        cudaEventCreateWithFlags(&evJoin, cudaEventDisableTiming);
    }

    // Fork branch A onto s2.
    cudaEventRecord(evFork, 0);
    cudaStreamWaitEvent(s2, evFork, 0);

    // Branch A: key-side (independent of query).
    k0_vk<<<32, 256, 0, s2>>>(ts, dg, Wt1, bt1, Wt2, bt2, Wg, bg);
    kB_dualmv<<<(S + 7) / 8, 256, 0, s2>>>((const float4*)key, S);
    cudaEventRecord(evJoin, s2);

    // Branch B: query-side scalar weights.
    k1_qsum<<<NPART, 256>>>((const float4*)query, S);
    k2a_qpart<<<32, 256>>>(Wa1, S);
    k2b_small<<<1, 256>>>(ts, dg, Wt1, bt1, Wt2, bt2, Wa1, ba1, Wa2, ba2);

    // Join and broadcast.
    cudaStreamWaitEvent(0, evJoin, 0);
    k4_bcast<<<S, 256>>>((float*)d_out, S);
}